// round 9
// baseline (speedup 1.0000x reference)
#include <cuda_runtime.h>
#include <cuda_bf16.h>
#include <cuda_fp16.h>

#define HH 1024
#define WW 2048
#define HWSZ (HH * WW)
#define NC 19
#define RAD 16
#define INV_LOG19 0.3396224f      // 1 / ln(19)
#define LOG2_TO_19 0.23541016f    // ln(2) / ln(19)

// -------- scratch (device globals: allocation-free per harness rules) -------
// packed per-pixel record: bits[16:21) = argmax class, bits[0:16) = fp16 wpe
__device__ unsigned g_packed[HWSZ];

// ============================================================================
// Pass A: per-pixel softmax entropy + argmax + weighted entropy -> packed 4B
// ============================================================================
__global__ __launch_bounds__(256) void passA(const float* __restrict__ logit,
                                             const float* __restrict__ cw) {
    int i = blockIdx.x * blockDim.x + threadIdx.x;
    if (i >= HWSZ) return;

    float v[NC];
#pragma unroll
    for (int c = 0; c < NC; c++) v[c] = logit[c * HWSZ + i];

    float m = v[0];
    int am = 0;
#pragma unroll
    for (int c = 1; c < NC; c++) {
        if (v[c] > m) { m = v[c]; am = c; }
    }

    float S = 0.f, T = 0.f;
#pragma unroll
    for (int c = 0; c < NC; c++) {
        float d = v[c] - m;
        float e = __expf(d);
        S += e;
        T += e * d;
    }
    float ent = __logf(S) - T * __frcp_rn(S);
    float wpe = ent * cw[am] * INV_LOG19;

    g_packed[i] = ((unsigned)am << 16)
                | (unsigned)__half_as_ushort(__float2half_rn(wpe));
}

// ============================================================================
// Fused passBC. Tile: 256 out-cols x 8 out-rows, grid (8,128)=1024 blocks.
// blockDim = 288 = W_IN (one vertical slider per column).
// smem: byte-packed records (24B/px) + 8-col group sums in h-format (48B/grp).
// ============================================================================
#define W_OUT 256
#define W_IN  288                  // + 2*RAD halo columns == blockDim
#define HB    8                    // output rows per block
#define CHC_F 8                    // outputs per horizontal-slider task
#define NGRP  (W_IN / 8)           // 36 column-groups per row
#define STRIDE_A (W_IN * 4 + 4)    // 1156 words; %32==4 -> r*4 distinct banks
#define STRIDE_B (W_IN * 2 + 2)    // 578 words;  %32==2 -> conflict-free
#define GRP_WORDS 12               // 10 h-words + fs + pad
#define SMEM_WORDS (HB * (STRIDE_A + STRIDE_B) + NGRP * HB * GRP_WORDS)
#define SMEM_BYTES (SMEM_WORDS * 4)   // 55488 + 13824 = 69312 B

__device__ __forceinline__ void pk_add(unsigned long long& w0,
                                       unsigned long long& w1,
                                       unsigned& w2, int cls) {
    if (cls < 8)       w0 += 1ull << (cls * 8);
    else if (cls < 16) w1 += 1ull << ((cls & 7) * 8);
    else               w2 += 1u << ((cls - 16) * 8);
}
__device__ __forceinline__ void pk_sub(unsigned long long& w0,
                                       unsigned long long& w1,
                                       unsigned& w2, int cls) {
    if (cls < 8)       w0 -= 1ull << (cls * 8);
    else if (cls < 16) w1 -= 1ull << ((cls & 7) * 8);
    else               w2 -= 1u << ((cls - 16) * 8);
}

// unpack 4 bytes into two u32 halfword pairs
#define PLO(w) __byte_perm((w), 0, 0x4140)
#define PHI(w) __byte_perm((w), 0, 0x4342)

__device__ __forceinline__ void srec_add(const unsigned* __restrict__ smA,
                                         const unsigned* __restrict__ smB,
                                         int s, unsigned* h, float& fs) {
    uint4 a = *(const uint4*)(smA + s * 4);
    uint2 b = *(const uint2*)(smB + s * 2);
    h[0] += PLO(a.x); h[1] += PHI(a.x);
    h[2] += PLO(a.y); h[3] += PHI(a.y);
    h[4] += PLO(a.z); h[5] += PHI(a.z);
    h[6] += PLO(a.w); h[7] += PHI(a.w);
    h[8] += PLO(b.x); h[9] += PHI(b.x);
    fs += __uint_as_float(b.y);
}
__device__ __forceinline__ void srec_sub(const unsigned* __restrict__ smA,
                                         const unsigned* __restrict__ smB,
                                         int s, unsigned* h, float& fs) {
    uint4 a = *(const uint4*)(smA + s * 4);
    uint2 b = *(const uint2*)(smB + s * 2);
    h[0] -= PLO(a.x); h[1] -= PHI(a.x);
    h[2] -= PLO(a.y); h[3] -= PHI(a.y);
    h[4] -= PLO(a.z); h[5] -= PHI(a.z);
    h[6] -= PLO(a.w); h[7] -= PHI(a.w);
    h[8] -= PLO(b.x); h[9] -= PHI(b.x);
    fs -= __uint_as_float(b.y);
}

// add one h-format group record (12 words) to accumulators
__device__ __forceinline__ void grp_add(const unsigned* __restrict__ g,
                                        unsigned* h, float& fs) {
    uint4 a = *(const uint4*)g;
    uint4 b = *(const uint4*)(g + 4);
    uint4 c = *(const uint4*)(g + 8);
    h[0] += a.x; h[1] += a.y; h[2] += a.z; h[3] += a.w;
    h[4] += b.x; h[5] += b.y; h[6] += b.z; h[7] += b.w;
    h[8] += c.x; h[9] += c.y;
    fs += __uint_as_float(c.z);
}

__global__ __launch_bounds__(W_IN, 3) void fusedBC(float* __restrict__ out) {
    extern __shared__ unsigned sm[];
    unsigned* smA = sm;                          // HB * STRIDE_A words
    unsigned* smB = sm + HB * STRIDE_A;          // HB * STRIDE_B words
    unsigned* smG = smB + HB * STRIDE_B;         // NGRP*HB*GRP_WORDS words
    const int x0 = blockIdx.x * W_OUT;
    const int y0 = blockIdx.y * HB;
    const int tid = threadIdx.x;

    // ------------- Phase 1: vertical 33-tap sliders, 1 column/thread --------
    {
        const int j = tid;                       // 0..287
        int xg = x0 - RAD + j;
        bool valid = (xg >= 0) && (xg < WW);

        unsigned long long w0 = 0, w1 = 0;
        unsigned w2 = 0;
        float fs = 0.f;
        if (valid) {
#pragma unroll
            for (int yi = 0; yi < 33; yi++) {
                int y = y0 - RAD + yi;
                if (y >= 0 && y < HH) {
                    unsigned u = g_packed[y * WW + xg];
                    fs += __half2float(__ushort_as_half((unsigned short)u));
                    pk_add(w0, w1, w2, (int)(u >> 16));
                }
            }
        }
#pragma unroll
        for (int r = 0; r < HB; r++) {
            *(uint4*)(smA + r * STRIDE_A + j * 4) =
                make_uint4((unsigned)w0, (unsigned)(w0 >> 32),
                           (unsigned)w1, (unsigned)(w1 >> 32));
            *(uint2*)(smB + r * STRIDE_B + j * 2) =
                make_uint2(w2, __float_as_uint(fs));
            if (valid) {
                int ya = y0 + r + RAD + 1;
                if (ya < HH) {
                    unsigned u = g_packed[ya * WW + xg];
                    fs += __half2float(__ushort_as_half((unsigned short)u));
                    pk_add(w0, w1, w2, (int)(u >> 16));
                }
                int yr = y0 + r - RAD;
                if (yr >= 0) {
                    unsigned u = g_packed[yr * WW + xg];
                    fs -= __half2float(__ushort_as_half((unsigned short)u));
                    pk_sub(w0, w1, w2, (int)(u >> 16));
                }
            }
        }
    }
    __syncthreads();

    // ------------- Phase 1.5: 8-column group sums (288 tasks = 36g x 8r) ----
    {
        const int r = tid & 7;                   // low bits: conflict-free LDS
        const int g = tid >> 3;                  // 0..35
        const unsigned* rowA = smA + r * STRIDE_A;
        const unsigned* rowB = smB + r * STRIDE_B;

        unsigned h[10];
#pragma unroll
        for (int i = 0; i < 10; i++) h[i] = 0;
        float fs = 0.f;
#pragma unroll
        for (int k = 0; k < 8; k++)
            srec_add(rowA, rowB, g * 8 + k, h, fs);

        unsigned* dst = smG + (g * 8 + r) * GRP_WORDS;
        *(uint4*)dst       = make_uint4(h[0], h[1], h[2], h[3]);
        *(uint4*)(dst + 4) = make_uint4(h[4], h[5], h[6], h[7]);
        *(uint4*)(dst + 8) = make_uint4(h[8], h[9], __float_as_uint(fs), 0u);
    }
    __syncthreads();

    // ------------- Phase 2: horizontal 33-tap sliders (256 tasks) -----------
    if (tid < 256) {
        const int r = tid & 7;      // low bits -> conflict-free LDS phases
        const int c = tid >> 3;
        const int xo = x0 + c * CHC_F;
        const unsigned* rowA = smA + r * STRIDE_A;
        const unsigned* rowB = smB + r * STRIDE_B;

        int yy = y0 + r;
        int wy = min(yy + RAD, HH - 1) - max(yy - RAD, 0) + 1;

        unsigned h[10];
#pragma unroll
        for (int i = 0; i < 10; i++) h[i] = 0;
        float fs = 0.f;

        // prime: groups c..c+3 cover local cols [8c, 8c+32), plus col 8c+32
#pragma unroll
        for (int i = 0; i < 4; i++)
            grp_add(smG + ((c + i) * 8 + r) * GRP_WORDS, h, fs);
        srec_add(rowA, rowB, c * CHC_F + 32, h, fs);

#pragma unroll
        for (int k4 = 0; k4 < CHC_F / 4; k4++) {
            float s4[4], i4[4], u4[4];
#pragma unroll
            for (int kk = 0; kk < 4; kk++) {
                int k = k4 * 4 + kk;
                int x = xo + k;
                int wx = min(x + RAD, WW - 1) - max(x - RAD, 0) + 1;
                float fcount = (float)(wx * wy);   // exact window size
                float invc = __frcp_rn(fcount);

                float acc0 = 0.f, acc1 = 0.f;      // two chains for ILP
#pragma unroll
                for (int p = 0; p < 10; p++) {
                    float slo = (float)(h[p] & 0xFFFFu);
                    float shi = (float)(h[p] >> 16);
                    acc0 += slo * __log2f(fmaxf(slo, 1.f));
                    if (p != 9)                    // lane 19 is zero pad
                        acc1 += shi * __log2f(fmaxf(shi, 1.f));
                }
                float impurity = (__log2f(fcount) - (acc0 + acc1) * invc)
                                 * LOG2_TO_19;
                float unc = fs * invc;

                s4[kk] = impurity * unc;
                i4[kk] = impurity;
                u4[kk] = unc;

                if (k < CHC_F - 1) {
                    srec_add(rowA, rowB, c * CHC_F + k + 33, h, fs);
                    srec_sub(rowA, rowB, c * CHC_F + k, h, fs);
                }
            }
            int o = yy * WW + xo + k4 * 4;
            *(float4*)(out + o)            = make_float4(s4[0], s4[1], s4[2], s4[3]);
            *(float4*)(out + HWSZ + o)     = make_float4(i4[0], i4[1], i4[2], i4[3]);
            *(float4*)(out + 2 * HWSZ + o) = make_float4(u4[0], u4[1], u4[2], u4[3]);
        }
    }
}

// ============================================================================
extern "C" void kernel_launch(void* const* d_in, const int* in_sizes, int n_in,
                              void* d_out, int out_size) {
    const float* logit = (const float*)d_in[0];
    const float* cw    = (const float*)d_in[1];
    float* out = (float*)d_out;

    cudaFuncSetAttribute(fusedBC, cudaFuncAttributeMaxDynamicSharedMemorySize,
                         SMEM_BYTES);

    passA<<<HWSZ / 256, 256>>>(logit, cw);
    fusedBC<<<dim3(WW / W_OUT, HH / HB), W_IN, SMEM_BYTES>>>(out);
}

// round 10
// speedup vs baseline: 1.2187x; 1.2187x over previous
#include <cuda_runtime.h>
#include <cuda_bf16.h>
#include <cuda_fp16.h>

#define HH 1024
#define WW 2048
#define HWSZ (HH * WW)
#define NC 19
#define RAD 16
#define INV_LOG19 0.3396224f      // 1 / ln(19)
#define LOG2_TO_19 0.23541016f    // ln(2) / ln(19)

// -------- scratch (device globals: allocation-free per harness rules) -------
// packed per-pixel record: bits[16:21) = argmax class, bits[0:16) = fp16 wpe
__device__ unsigned g_packed[HWSZ];

// ============================================================================
// Pass A: per-pixel softmax entropy + argmax + weighted entropy -> packed 4B
// ============================================================================
__global__ __launch_bounds__(256) void passA(const float* __restrict__ logit,
                                             const float* __restrict__ cw) {
    int i = blockIdx.x * blockDim.x + threadIdx.x;
    if (i >= HWSZ) return;

    float v[NC];
#pragma unroll
    for (int c = 0; c < NC; c++) v[c] = logit[c * HWSZ + i];

    float m = v[0];
    int am = 0;
#pragma unroll
    for (int c = 1; c < NC; c++) {
        if (v[c] > m) { m = v[c]; am = c; }
    }

    float S = 0.f, T = 0.f;
#pragma unroll
    for (int c = 0; c < NC; c++) {
        float d = v[c] - m;
        float e = __expf(d);
        S += e;
        T += e * d;
    }
    float ent = __logf(S) - T * __frcp_rn(S);
    float wpe = ent * cw[am] * INV_LOG19;

    g_packed[i] = ((unsigned)am << 16)
                | (unsigned)__half_as_ushort(__float2half_rn(wpe));
}

// ============================================================================
// Fused passBC. Tile: 224 out-cols x 8 out-rows, grid (10,128).
// blockDim = 256 = W_IN: one vertical slider per thread (no straggler),
// smem 49.3KB + 64 regs -> 4 blocks/SM with L1 headroom (no spill pressure).
// ============================================================================
#define W_OUT 224
#define W_IN  256                  // + 2*RAD halo columns == blockDim
#define HB    8                    // output rows per block
#define CHC_F 8                    // outputs per horizontal-slider task
#define NCHK  (W_OUT / CHC_F)      // 28 chunks per row
#define STRIDE_A (W_IN * 4 + 4)    // 1028 words; %32==4 -> r*4 distinct banks
#define STRIDE_B (W_IN * 2 + 2)    // 514 words;  %32==2 -> conflict-free
#define SMEM_WORDS (HB * (STRIDE_A + STRIDE_B))
#define SMEM_BYTES (SMEM_WORDS * 4)   // 49344 B

__device__ __forceinline__ void pk_add(unsigned long long& w0,
                                       unsigned long long& w1,
                                       unsigned& w2, int cls) {
    if (cls < 8)       w0 += 1ull << (cls * 8);
    else if (cls < 16) w1 += 1ull << ((cls & 7) * 8);
    else               w2 += 1u << ((cls - 16) * 8);
}
__device__ __forceinline__ void pk_sub(unsigned long long& w0,
                                       unsigned long long& w1,
                                       unsigned& w2, int cls) {
    if (cls < 8)       w0 -= 1ull << (cls * 8);
    else if (cls < 16) w1 -= 1ull << ((cls & 7) * 8);
    else               w2 -= 1u << ((cls - 16) * 8);
}

// unpack 4 bytes into two u32 halfword pairs
#define PLO(w) __byte_perm((w), 0, 0x4140)
#define PHI(w) __byte_perm((w), 0, 0x4342)

__device__ __forceinline__ void srec_add(const unsigned* __restrict__ smA,
                                         const unsigned* __restrict__ smB,
                                         int s, unsigned* h, float& fs) {
    uint4 a = *(const uint4*)(smA + s * 4);
    uint2 b = *(const uint2*)(smB + s * 2);
    h[0] += PLO(a.x); h[1] += PHI(a.x);
    h[2] += PLO(a.y); h[3] += PHI(a.y);
    h[4] += PLO(a.z); h[5] += PHI(a.z);
    h[6] += PLO(a.w); h[7] += PHI(a.w);
    h[8] += PLO(b.x); h[9] += PHI(b.x);
    fs += __uint_as_float(b.y);
}
__device__ __forceinline__ void srec_sub(const unsigned* __restrict__ smA,
                                         const unsigned* __restrict__ smB,
                                         int s, unsigned* h, float& fs) {
    uint4 a = *(const uint4*)(smA + s * 4);
    uint2 b = *(const uint2*)(smB + s * 2);
    h[0] -= PLO(a.x); h[1] -= PHI(a.x);
    h[2] -= PLO(a.y); h[3] -= PHI(a.y);
    h[4] -= PLO(a.z); h[5] -= PHI(a.z);
    h[6] -= PLO(a.w); h[7] -= PHI(a.w);
    h[8] -= PLO(b.x); h[9] -= PHI(b.x);
    fs -= __uint_as_float(b.y);
}

__global__ __launch_bounds__(W_IN, 4) void fusedBC(float* __restrict__ out) {
    extern __shared__ unsigned sm[];
    unsigned* smA = sm;                          // HB * STRIDE_A words
    unsigned* smB = sm + HB * STRIDE_A;          // HB * STRIDE_B words
    const int x0 = blockIdx.x * W_OUT;
    const int y0 = blockIdx.y * HB;
    const int tid = threadIdx.x;

    // ------------- Phase 1: vertical 33-tap sliders, 1 column/thread --------
    {
        const int j = tid;                       // 0..255
        int xg = x0 - RAD + j;
        bool valid = (xg >= 0) && (xg < WW);

        unsigned long long w0 = 0, w1 = 0;
        unsigned w2 = 0;
        float fs = 0.f;
        if (valid) {
#pragma unroll
            for (int yi = 0; yi < 33; yi++) {
                int y = y0 - RAD + yi;
                if (y >= 0 && y < HH) {
                    unsigned u = g_packed[y * WW + xg];
                    fs += __half2float(__ushort_as_half((unsigned short)u));
                    pk_add(w0, w1, w2, (int)(u >> 16));
                }
            }
        }
#pragma unroll
        for (int r = 0; r < HB; r++) {
            *(uint4*)(smA + r * STRIDE_A + j * 4) =
                make_uint4((unsigned)w0, (unsigned)(w0 >> 32),
                           (unsigned)w1, (unsigned)(w1 >> 32));
            *(uint2*)(smB + r * STRIDE_B + j * 2) =
                make_uint2(w2, __float_as_uint(fs));
            if (valid) {
                int ya = y0 + r + RAD + 1;
                if (ya < HH) {
                    unsigned u = g_packed[ya * WW + xg];
                    fs += __half2float(__ushort_as_half((unsigned short)u));
                    pk_add(w0, w1, w2, (int)(u >> 16));
                }
                int yr = y0 + r - RAD;
                if (yr >= 0) {
                    unsigned u = g_packed[yr * WW + xg];
                    fs -= __half2float(__ushort_as_half((unsigned short)u));
                    pk_sub(w0, w1, w2, (int)(u >> 16));
                }
            }
        }
    }
    __syncthreads();

    // ------------- Phase 2: horizontal 33-tap sliders (224 tasks) -----------
    {
        const int r = tid & 7;      // low bits -> conflict-free LDS phases
        const int c = tid >> 3;     // 0..31; chunks 28..31 idle
        const int xo = x0 + c * CHC_F;
        if (c < NCHK && xo < WW) {
            const unsigned* rowA = smA + r * STRIDE_A;
            const unsigned* rowB = smB + r * STRIDE_B;

            int yy = y0 + r;
            int wy = min(yy + RAD, HH - 1) - max(yy - RAD, 0) + 1;

            unsigned h[10];
#pragma unroll
            for (int i = 0; i < 10; i++) h[i] = 0;
            float fs = 0.f;

#pragma unroll
            for (int si = 0; si < 33; si++)
                srec_add(rowA, rowB, c * CHC_F + si, h, fs);

#pragma unroll
            for (int k4 = 0; k4 < CHC_F / 4; k4++) {
                float s4[4], i4[4], u4[4];
#pragma unroll
                for (int kk = 0; kk < 4; kk++) {
                    int k = k4 * 4 + kk;
                    int x = xo + k;
                    int wx = min(x + RAD, WW - 1) - max(x - RAD, 0) + 1;
                    float fcount = (float)(wx * wy);   // exact window size
                    float invc = __frcp_rn(fcount);

                    float acc0 = 0.f, acc1 = 0.f;      // two chains for ILP
#pragma unroll
                    for (int p = 0; p < 10; p++) {
                        float slo = (float)(h[p] & 0xFFFFu);
                        float shi = (float)(h[p] >> 16);
                        acc0 += slo * __log2f(fmaxf(slo, 1.f));
                        if (p != 9)                    // lane 19 is zero pad
                            acc1 += shi * __log2f(fmaxf(shi, 1.f));
                    }
                    float impurity = (__log2f(fcount) - (acc0 + acc1) * invc)
                                     * LOG2_TO_19;
                    float unc = fs * invc;

                    s4[kk] = impurity * unc;
                    i4[kk] = impurity;
                    u4[kk] = unc;

                    if (k < CHC_F - 1) {
                        srec_add(rowA, rowB, c * CHC_F + k + 33, h, fs);
                        srec_sub(rowA, rowB, c * CHC_F + k, h, fs);
                    }
                }
                int o = yy * WW + xo + k4 * 4;
                *(float4*)(out + o)            = make_float4(s4[0], s4[1], s4[2], s4[3]);
                *(float4*)(out + HWSZ + o)     = make_float4(i4[0], i4[1], i4[2], i4[3]);
                *(float4*)(out + 2 * HWSZ + o) = make_float4(u4[0], u4[1], u4[2], u4[3]);
            }
        }
    }
}

// ============================================================================
extern "C" void kernel_launch(void* const* d_in, const int* in_sizes, int n_in,
                              void* d_out, int out_size) {
    const float* logit = (const float*)d_in[0];
    const float* cw    = (const float*)d_in[1];
    float* out = (float*)d_out;

    cudaFuncSetAttribute(fusedBC, cudaFuncAttributeMaxDynamicSharedMemorySize,
                         SMEM_BYTES);

    passA<<<HWSZ / 256, 256>>>(logit, cw);
    fusedBC<<<dim3((WW + W_OUT - 1) / W_OUT, HH / HB), W_IN, SMEM_BYTES>>>(out);
}

// round 11
// speedup vs baseline: 1.2989x; 1.0658x over previous
#include <cuda_runtime.h>
#include <cuda_bf16.h>
#include <cuda_fp16.h>

#define HH 1024
#define WW 2048
#define HWSZ (HH * WW)
#define NC 19
#define RAD 16
#define INV_LOG19 0.3396224f      // 1 / ln(19)
#define LOG2_TO_19 0.23541016f    // ln(2) / ln(19)

// -------- scratch (device globals: allocation-free per harness rules) -------
// packed per-pixel record: bits[16:21) = argmax class, bits[0:16) = fp16 wpe
__device__ unsigned g_packed[HWSZ];

// ============================================================================
// Pass A: per-pixel softmax entropy + argmax + weighted entropy -> packed 4B
// ============================================================================
__global__ __launch_bounds__(256) void passA(const float* __restrict__ logit,
                                             const float* __restrict__ cw) {
    int i = blockIdx.x * blockDim.x + threadIdx.x;
    if (i >= HWSZ) return;

    float v[NC];
#pragma unroll
    for (int c = 0; c < NC; c++) v[c] = logit[c * HWSZ + i];

    float m = v[0];
    int am = 0;
#pragma unroll
    for (int c = 1; c < NC; c++) {
        if (v[c] > m) { m = v[c]; am = c; }
    }

    float S = 0.f, T = 0.f;
#pragma unroll
    for (int c = 0; c < NC; c++) {
        float d = v[c] - m;
        float e = __expf(d);
        S += e;
        T += e * d;
    }
    float ent = __logf(S) - T * __frcp_rn(S);
    float wpe = ent * cw[am] * INV_LOG19;

    g_packed[i] = ((unsigned)am << 16)
                | (unsigned)__half_as_ushort(__float2half_rn(wpe));
}

// ============================================================================
// Fused passBC. Tile: 224 out-cols x 8 out-rows, grid (10,128).
// blockDim = 256 = W_IN (one vertical slider per thread).
// launch_bounds(256,3): ~84 regs for deep load batching / pipelining.
// Sentinel class 19 (0x00130000) makes all loads branchless; it lands in
// w2 byte 3 whose h[9]-high lane is excluded from entropy and count.
// ============================================================================
#define W_OUT 224
#define W_IN  256                  // + 2*RAD halo columns == blockDim
#define HB    8                    // output rows per block
#define CHC_F 8                    // outputs per horizontal-slider task
#define NCHK  (W_OUT / CHC_F)      // 28 chunks per row
#define STRIDE_A (W_IN * 4 + 4)    // 1028 words; %32==4 -> conflict-free
#define STRIDE_B (W_IN * 2 + 2)    // 514 words;  %32==2 -> conflict-free
#define SMEM_WORDS (HB * (STRIDE_A + STRIDE_B))
#define SMEM_BYTES (SMEM_WORDS * 4)   // 49344 B
#define SENT 0x00130000u           // class 19, wpe payload 0

__device__ __forceinline__ void pk_add(unsigned long long& w0,
                                       unsigned long long& w1,
                                       unsigned& w2, int cls) {
    if (cls < 8)       w0 += 1ull << (cls * 8);
    else if (cls < 16) w1 += 1ull << ((cls & 7) * 8);
    else               w2 += 1u << ((cls - 16) * 8);   // cls 19 -> spare byte 3
}
__device__ __forceinline__ void pk_sub(unsigned long long& w0,
                                       unsigned long long& w1,
                                       unsigned& w2, int cls) {
    if (cls < 8)       w0 -= 1ull << (cls * 8);
    else if (cls < 16) w1 -= 1ull << ((cls & 7) * 8);
    else               w2 -= 1u << ((cls - 16) * 8);
}

// unpack 4 bytes into two u32 halfword pairs
#define PLO(w) __byte_perm((w), 0, 0x4140)
#define PHI(w) __byte_perm((w), 0, 0x4342)

__device__ __forceinline__ float h2f_lo(unsigned u) {
    return __half2float(__ushort_as_half((unsigned short)u));
}

__device__ __forceinline__ void apply_add(uint4 a, uint2 b,
                                          unsigned* h, float& fs) {
    h[0] += PLO(a.x); h[1] += PHI(a.x);
    h[2] += PLO(a.y); h[3] += PHI(a.y);
    h[4] += PLO(a.z); h[5] += PHI(a.z);
    h[6] += PLO(a.w); h[7] += PHI(a.w);
    h[8] += PLO(b.x); h[9] += PHI(b.x);
    fs += __uint_as_float(b.y);
}
__device__ __forceinline__ void apply_sub(uint4 a, uint2 b,
                                          unsigned* h, float& fs) {
    h[0] -= PLO(a.x); h[1] -= PHI(a.x);
    h[2] -= PLO(a.y); h[3] -= PHI(a.y);
    h[4] -= PLO(a.z); h[5] -= PHI(a.z);
    h[6] -= PLO(a.w); h[7] -= PHI(a.w);
    h[8] -= PLO(b.x); h[9] -= PHI(b.x);
    fs -= __uint_as_float(b.y);
}

__global__ __launch_bounds__(W_IN, 3) void fusedBC(float* __restrict__ out) {
    extern __shared__ unsigned sm[];
    unsigned* smA = sm;                          // HB * STRIDE_A words
    unsigned* smB = sm + HB * STRIDE_A;          // HB * STRIDE_B words
    const int x0 = blockIdx.x * W_OUT;
    const int y0 = blockIdx.y * HB;
    const int tid = threadIdx.x;

    // ------------- Phase 1: vertical 33-tap sliders, branchless -------------
    {
        int xg = x0 - RAD + tid;
        bool xv = (xg >= 0) && (xg < WW);
        int xc = min(max(xg, 0), WW - 1);        // safe address, value gated

        unsigned long long w0 = 0, w1 = 0;
        unsigned w2 = 0;
        float fs = 0.f;
#pragma unroll
        for (int yi = 0; yi < 33; yi++) {
            int y = y0 - RAD + yi;
            bool inb = xv && (y >= 0) && (y < HH);
            unsigned u = inb ? g_packed[y * WW + xc] : SENT;
            fs += h2f_lo(u);
            pk_add(w0, w1, w2, (int)(u >> 16));
        }

        // batch all 16 slide words (MLP = 16, no dependency on the r-loop)
        unsigned ua[HB], ud[HB];
#pragma unroll
        for (int r = 0; r < HB; r++) {
            int ya = y0 + r + RAD + 1;
            ua[r] = (xv && (ya < HH)) ? g_packed[ya * WW + xc] : SENT;
            int yr = y0 + r - RAD;
            ud[r] = (xv && (yr >= 0)) ? g_packed[yr * WW + xc] : SENT;
        }

#pragma unroll
        for (int r = 0; r < HB; r++) {
            *(uint4*)(smA + r * STRIDE_A + tid * 4) =
                make_uint4((unsigned)w0, (unsigned)(w0 >> 32),
                           (unsigned)w1, (unsigned)(w1 >> 32));
            *(uint2*)(smB + r * STRIDE_B + tid * 2) =
                make_uint2(w2, __float_as_uint(fs));
            fs += h2f_lo(ua[r]);
            pk_add(w0, w1, w2, (int)(ua[r] >> 16));
            fs -= h2f_lo(ud[r]);
            pk_sub(w0, w1, w2, (int)(ud[r] >> 16));
        }
    }
    __syncthreads();

    // ------------- Phase 2: horizontal sliders, software-pipelined ----------
    {
        const int r = tid & 7;      // low bits -> conflict-free LDS phases
        const int c = tid >> 3;     // 0..31; chunks >= NCHK idle
        const int xo = x0 + c * CHC_F;
        if (c < NCHK && xo < WW) {
            const unsigned* rowA = smA + r * STRIDE_A;
            const unsigned* rowB = smB + r * STRIDE_B;

            int yy = y0 + r;
            int wy = min(yy + RAD, HH - 1) - max(yy - RAD, 0) + 1;

            unsigned h[10];
#pragma unroll
            for (int i = 0; i < 10; i++) h[i] = 0;
            float fs = 0.f;

#pragma unroll
            for (int si = 0; si < 33; si++) {
                int s = c * CHC_F + si;
                apply_add(*(const uint4*)(rowA + s * 4),
                          *(const uint2*)(rowB + s * 2), h, fs);
            }

            float s4[4], i4[4], u4[4];
#pragma unroll
            for (int k = 0; k < CHC_F; k++) {
                // ---- prefetch next slide's records BEFORE entropy ----
                uint4 aN, aO; uint2 bN, bO;
                if (k < CHC_F - 1) {
                    int sN = c * CHC_F + k + 33;
                    int sO = c * CHC_F + k;
                    aN = *(const uint4*)(rowA + sN * 4);
                    bN = *(const uint2*)(rowB + sN * 2);
                    aO = *(const uint4*)(rowA + sO * 4);
                    bO = *(const uint2*)(rowB + sO * 2);
                }

                // ---- entropy of current window (LDS latency hides here) ----
                int x = xo + k;
                int wx = min(x + RAD, WW - 1) - max(x - RAD, 0) + 1;
                float fcount = (float)(wx * wy);   // exact window size
                float invc = __frcp_rn(fcount);

                float acc0 = 0.f, acc1 = 0.f;      // two chains for ILP
#pragma unroll
                for (int p = 0; p < 10; p++) {
                    float slo = (float)(h[p] & 0xFFFFu);
                    float shi = (float)(h[p] >> 16);
                    acc0 += slo * __log2f(fmaxf(slo, 1.f));
                    if (p != 9)                    // lane 19 is pad/sentinel
                        acc1 += shi * __log2f(fmaxf(shi, 1.f));
                }
                float impurity = (__log2f(fcount) - (acc0 + acc1) * invc)
                                 * LOG2_TO_19;
                float unc = fs * invc;

                s4[k & 3] = impurity * unc;
                i4[k & 3] = impurity;
                u4[k & 3] = unc;

                if ((k & 3) == 3) {
                    int o = yy * WW + xo + (k & ~3);
                    *(float4*)(out + o)            = make_float4(s4[0], s4[1], s4[2], s4[3]);
                    *(float4*)(out + HWSZ + o)     = make_float4(i4[0], i4[1], i4[2], i4[3]);
                    *(float4*)(out + 2 * HWSZ + o) = make_float4(u4[0], u4[1], u4[2], u4[3]);
                }

                // ---- apply the prefetched slide ----
                if (k < CHC_F - 1) {
                    apply_add(aN, bN, h, fs);
                    apply_sub(aO, bO, h, fs);
                }
            }
        }
    }
}

// ============================================================================
extern "C" void kernel_launch(void* const* d_in, const int* in_sizes, int n_in,
                              void* d_out, int out_size) {
    const float* logit = (const float*)d_in[0];
    const float* cw    = (const float*)d_in[1];
    float* out = (float*)d_out;

    cudaFuncSetAttribute(fusedBC, cudaFuncAttributeMaxDynamicSharedMemorySize,
                         SMEM_BYTES);

    passA<<<HWSZ / 256, 256>>>(logit, cw);
    fusedBC<<<dim3((WW + W_OUT - 1) / W_OUT, HH / HB), W_IN, SMEM_BYTES>>>(out);
}

// round 12
// speedup vs baseline: 1.4315x; 1.1020x over previous
#include <cuda_runtime.h>
#include <cuda_bf16.h>
#include <cuda_fp16.h>

#define HH 1024
#define WW 2048
#define HWSZ (HH * WW)
#define NC 19
#define RAD 16
#define INV_LOG19 0.3396224f      // 1 / ln(19)
#define LOG2_TO_19 0.23541016f    // ln(2) / ln(19)

// -------- scratch (device globals: allocation-free per harness rules) -------
// packed per-pixel record: bits[16:21) = argmax class, bits[0:16) = fp16 wpe
__device__ unsigned g_packed[HWSZ];

// ============================================================================
// Pass A: 4 pixels/thread via float4 (19 LDG.128, MLP=19), packed 4B output
// ============================================================================
__global__ __launch_bounds__(128) void passA(const float4* __restrict__ logit4,
                                             const float* __restrict__ cw) {
    int i = blockIdx.x * 128 + threadIdx.x;     // float4-group index
    if (i >= HWSZ / 4) return;

    float4 v[NC];
#pragma unroll
    for (int c = 0; c < NC; c++) v[c] = logit4[c * (HWSZ / 4) + i];

    unsigned outw[4];
#pragma unroll
    for (int l = 0; l < 4; l++) {
        float x[NC];
#pragma unroll
        for (int c = 0; c < NC; c++)
            x[c] = (l == 0) ? v[c].x : (l == 1) ? v[c].y
                 : (l == 2) ? v[c].z : v[c].w;

        float m = x[0];
        int am = 0;
#pragma unroll
        for (int c = 1; c < NC; c++) {
            if (x[c] > m) { m = x[c]; am = c; }
        }

        float S = 0.f, T = 0.f;
#pragma unroll
        for (int c = 0; c < NC; c++) {
            float d = x[c] - m;
            float e = __expf(d);
            S += e;
            T += e * d;
        }
        float ent = __logf(S) - T * __frcp_rn(S);
        float wpe = ent * cw[am] * INV_LOG19;

        outw[l] = ((unsigned)am << 16)
                | (unsigned)__half_as_ushort(__float2half_rn(wpe));
    }
    *(uint4*)(g_packed + 4 * i) = make_uint4(outw[0], outw[1], outw[2], outw[3]);
}

// ============================================================================
// Fused passBC. Tile: 224 out-cols x 8 out-rows, grid (10,128).
// blockDim = 256 = W_IN (one vertical slider per thread).
// Phase 1.5 builds 8-column group sums in smem (h-format) so phase 2's
// 33-record prime collapses to 4 group-adds + 1 record-add.
// Sentinel class 19 keeps everything branchless (lands in excluded lane).
// ============================================================================
#define W_OUT 224
#define W_IN  256                  // + 2*RAD halo columns == blockDim
#define HB    8                    // output rows per block
#define CHC_F 8                    // outputs per horizontal-slider task
#define NCHK  (W_OUT / CHC_F)      // 28 chunks per row
#define NGRP  (W_IN / CHC_F)       // 32 column-groups
#define STRIDE_A (W_IN * 4 + 4)    // 1028 words; %32==4 -> conflict-free
#define STRIDE_B (W_IN * 2 + 2)    // 514 words;  %32==2 -> conflict-free
#define GRP_WORDS 12               // 10 h-words + fs + pad (48B, 16B-aligned)
#define SMEM_WORDS (HB * (STRIDE_A + STRIDE_B) + NGRP * HB * GRP_WORDS)
#define SMEM_BYTES (SMEM_WORDS * 4)   // 49344 + 12288 = 61632 B
#define SENT 0x00130000u           // class 19, wpe payload 0

__device__ __forceinline__ void pk_add(unsigned long long& w0,
                                       unsigned long long& w1,
                                       unsigned& w2, int cls) {
    if (cls < 8)       w0 += 1ull << (cls * 8);
    else if (cls < 16) w1 += 1ull << ((cls & 7) * 8);
    else               w2 += 1u << ((cls - 16) * 8);   // cls 19 -> spare byte 3
}
__device__ __forceinline__ void pk_sub(unsigned long long& w0,
                                       unsigned long long& w1,
                                       unsigned& w2, int cls) {
    if (cls < 8)       w0 -= 1ull << (cls * 8);
    else if (cls < 16) w1 -= 1ull << ((cls & 7) * 8);
    else               w2 -= 1u << ((cls - 16) * 8);
}

// unpack 4 bytes into two u32 halfword pairs
#define PLO(w) __byte_perm((w), 0, 0x4140)
#define PHI(w) __byte_perm((w), 0, 0x4342)

__device__ __forceinline__ float h2f_lo(unsigned u) {
    return __half2float(__ushort_as_half((unsigned short)u));
}

__device__ __forceinline__ void apply_add(uint4 a, uint2 b,
                                          unsigned* h, float& fs) {
    h[0] += PLO(a.x); h[1] += PHI(a.x);
    h[2] += PLO(a.y); h[3] += PHI(a.y);
    h[4] += PLO(a.z); h[5] += PHI(a.z);
    h[6] += PLO(a.w); h[7] += PHI(a.w);
    h[8] += PLO(b.x); h[9] += PHI(b.x);
    fs += __uint_as_float(b.y);
}
__device__ __forceinline__ void apply_sub(uint4 a, uint2 b,
                                          unsigned* h, float& fs) {
    h[0] -= PLO(a.x); h[1] -= PHI(a.x);
    h[2] -= PLO(a.y); h[3] -= PHI(a.y);
    h[4] -= PLO(a.z); h[5] -= PHI(a.z);
    h[6] -= PLO(a.w); h[7] -= PHI(a.w);
    h[8] -= PLO(b.x); h[9] -= PHI(b.x);
    fs -= __uint_as_float(b.y);
}

// add one h-format group record (12 words) to accumulators
__device__ __forceinline__ void grp_add(const unsigned* __restrict__ g,
                                        unsigned* h, float& fs) {
    uint4 a = *(const uint4*)g;
    uint4 b = *(const uint4*)(g + 4);
    uint4 c = *(const uint4*)(g + 8);
    h[0] += a.x; h[1] += a.y; h[2] += a.z; h[3] += a.w;
    h[4] += b.x; h[5] += b.y; h[6] += b.z; h[7] += b.w;
    h[8] += c.x; h[9] += c.y;
    fs += __uint_as_float(c.z);
}

__global__ __launch_bounds__(W_IN, 3) void fusedBC(float* __restrict__ out) {
    extern __shared__ unsigned sm[];
    unsigned* smA = sm;                          // HB * STRIDE_A words
    unsigned* smB = sm + HB * STRIDE_A;          // HB * STRIDE_B words
    unsigned* smG = smB + HB * STRIDE_B;         // NGRP*HB*GRP_WORDS words
    const int x0 = blockIdx.x * W_OUT;
    const int y0 = blockIdx.y * HB;
    const int tid = threadIdx.x;

    // ------------- Phase 1: vertical 33-tap sliders, branchless -------------
    {
        int xg = x0 - RAD + tid;
        bool xv = (xg >= 0) && (xg < WW);
        int xc = min(max(xg, 0), WW - 1);        // safe address, value gated

        unsigned long long w0 = 0, w1 = 0;
        unsigned w2 = 0;
        float fs = 0.f;
#pragma unroll
        for (int yi = 0; yi < 33; yi++) {
            int y = y0 - RAD + yi;
            bool inb = xv && (y >= 0) && (y < HH);
            unsigned u = inb ? g_packed[y * WW + xc] : SENT;
            fs += h2f_lo(u);
            pk_add(w0, w1, w2, (int)(u >> 16));
        }

        // batch all 16 slide words (MLP = 16)
        unsigned ua[HB], ud[HB];
#pragma unroll
        for (int r = 0; r < HB; r++) {
            int ya = y0 + r + RAD + 1;
            ua[r] = (xv && (ya < HH)) ? g_packed[ya * WW + xc] : SENT;
            int yr = y0 + r - RAD;
            ud[r] = (xv && (yr >= 0)) ? g_packed[yr * WW + xc] : SENT;
        }

#pragma unroll
        for (int r = 0; r < HB; r++) {
            *(uint4*)(smA + r * STRIDE_A + tid * 4) =
                make_uint4((unsigned)w0, (unsigned)(w0 >> 32),
                           (unsigned)w1, (unsigned)(w1 >> 32));
            *(uint2*)(smB + r * STRIDE_B + tid * 2) =
                make_uint2(w2, __float_as_uint(fs));
            fs += h2f_lo(ua[r]);
            pk_add(w0, w1, w2, (int)(ua[r] >> 16));
            fs -= h2f_lo(ud[r]);
            pk_sub(w0, w1, w2, (int)(ud[r] >> 16));
        }
    }
    __syncthreads();

    // ------------- Phase 1.5: 8-col group sums (256 tasks = 32g x 8r) -------
    {
        const int r = tid & 7;                   // low bits: conflict-free LDS
        const int g = tid >> 3;                  // 0..31
        const unsigned* rowA = smA + r * STRIDE_A;
        const unsigned* rowB = smB + r * STRIDE_B;

        unsigned h[10];
#pragma unroll
        for (int i = 0; i < 10; i++) h[i] = 0;
        float fs = 0.f;
#pragma unroll
        for (int k = 0; k < 8; k++) {
            int s = g * 8 + k;
            apply_add(*(const uint4*)(rowA + s * 4),
                      *(const uint2*)(rowB + s * 2), h, fs);
        }
        unsigned* dst = smG + (g * 8 + r) * GRP_WORDS;
        *(uint4*)dst       = make_uint4(h[0], h[1], h[2], h[3]);
        *(uint4*)(dst + 4) = make_uint4(h[4], h[5], h[6], h[7]);
        *(uint4*)(dst + 8) = make_uint4(h[8], h[9], __float_as_uint(fs), 0u);
    }
    __syncthreads();

    // ------------- Phase 2: horizontal sliders, software-pipelined ----------
    {
        const int r = tid & 7;      // low bits -> conflict-free LDS phases
        const int c = tid >> 3;     // 0..31; chunks >= NCHK idle
        const int xo = x0 + c * CHC_F;
        if (c < NCHK && xo < WW) {
            const unsigned* rowA = smA + r * STRIDE_A;
            const unsigned* rowB = smB + r * STRIDE_B;

            int yy = y0 + r;
            int wy = min(yy + RAD, HH - 1) - max(yy - RAD, 0) + 1;

            unsigned h[10];
#pragma unroll
            for (int i = 0; i < 10; i++) h[i] = 0;
            float fs = 0.f;

            // prime: groups c..c+3 cover records [8c, 8c+32), + record 8c+32
#pragma unroll
            for (int i = 0; i < 4; i++)
                grp_add(smG + ((c + i) * 8 + r) * GRP_WORDS, h, fs);
            {
                int s = c * CHC_F + 32;
                apply_add(*(const uint4*)(rowA + s * 4),
                          *(const uint2*)(rowB + s * 2), h, fs);
            }

            float s4[4], i4[4], u4[4];
#pragma unroll
            for (int k = 0; k < CHC_F; k++) {
                // ---- prefetch next slide's records BEFORE entropy ----
                uint4 aN, aO; uint2 bN, bO;
                if (k < CHC_F - 1) {
                    int sN = c * CHC_F + k + 33;
                    int sO = c * CHC_F + k;
                    aN = *(const uint4*)(rowA + sN * 4);
                    bN = *(const uint2*)(rowB + sN * 2);
                    aO = *(const uint4*)(rowA + sO * 4);
                    bO = *(const uint2*)(rowB + sO * 2);
                }

                // ---- entropy of current window (LDS latency hides here) ----
                int x = xo + k;
                int wx = min(x + RAD, WW - 1) - max(x - RAD, 0) + 1;
                float fcount = (float)(wx * wy);   // exact window size
                float invc = __frcp_rn(fcount);

                float acc0 = 0.f, acc1 = 0.f;      // two chains for ILP
#pragma unroll
                for (int p = 0; p < 10; p++) {
                    float slo = (float)(h[p] & 0xFFFFu);
                    float shi = (float)(h[p] >> 16);
                    acc0 += slo * __log2f(fmaxf(slo, 1.f));
                    if (p != 9)                    // lane 19 is pad/sentinel
                        acc1 += shi * __log2f(fmaxf(shi, 1.f));
                }
                float impurity = (__log2f(fcount) - (acc0 + acc1) * invc)
                                 * LOG2_TO_19;
                float unc = fs * invc;

                s4[k & 3] = impurity * unc;
                i4[k & 3] = impurity;
                u4[k & 3] = unc;

                if ((k & 3) == 3) {
                    int o = yy * WW + xo + (k & ~3);
                    *(float4*)(out + o)            = make_float4(s4[0], s4[1], s4[2], s4[3]);
                    *(float4*)(out + HWSZ + o)     = make_float4(i4[0], i4[1], i4[2], i4[3]);
                    *(float4*)(out + 2 * HWSZ + o) = make_float4(u4[0], u4[1], u4[2], u4[3]);
                }

                // ---- apply the prefetched slide ----
                if (k < CHC_F - 1) {
                    apply_add(aN, bN, h, fs);
                    apply_sub(aO, bO, h, fs);
                }
            }
        }
    }
}

// ============================================================================
extern "C" void kernel_launch(void* const* d_in, const int* in_sizes, int n_in,
                              void* d_out, int out_size) {
    const float* logit = (const float*)d_in[0];
    const float* cw    = (const float*)d_in[1];
    float* out = (float*)d_out;

    cudaFuncSetAttribute(fusedBC, cudaFuncAttributeMaxDynamicSharedMemorySize,
                         SMEM_BYTES);

    passA<<<(HWSZ / 4) / 128, 128>>>((const float4*)logit, cw);
    fusedBC<<<dim3((WW + W_OUT - 1) / W_OUT, HH / HB), W_IN, SMEM_BYTES>>>(out);
}

// round 13
// speedup vs baseline: 1.4575x; 1.0182x over previous
#include <cuda_runtime.h>
#include <cuda_bf16.h>
#include <cuda_fp16.h>

#define HH 1024
#define WW 2048
#define HWSZ (HH * WW)
#define NC 19
#define RAD 16
#define INV_LOG19 0.3396224f      // 1 / ln(19)
#define LOG2_TO_19 0.23541016f    // ln(2) / ln(19)

// -------- scratch (device globals: allocation-free per harness rules) -------
// packed per-pixel record: bits[16:21) = argmax class, bits[0:16) = fp16 wpe
__device__ unsigned g_packed[HWSZ];

// ============================================================================
// Pass A: per-pixel softmax entropy + argmax + weighted entropy -> packed 4B
// (scalar version: proven 27.1us / 72% DRAM; float4 variant regressed)
// ============================================================================
__global__ __launch_bounds__(256) void passA(const float* __restrict__ logit,
                                             const float* __restrict__ cw) {
    int i = blockIdx.x * blockDim.x + threadIdx.x;
    if (i >= HWSZ) return;

    float v[NC];
#pragma unroll
    for (int c = 0; c < NC; c++) v[c] = logit[c * HWSZ + i];

    float m = v[0];
    int am = 0;
#pragma unroll
    for (int c = 1; c < NC; c++) {
        if (v[c] > m) { m = v[c]; am = c; }
    }

    float S = 0.f, T = 0.f;
#pragma unroll
    for (int c = 0; c < NC; c++) {
        float d = v[c] - m;
        float e = __expf(d);
        S += e;
        T += e * d;
    }
    float ent = __logf(S) - T * __frcp_rn(S);
    float wpe = ent * cw[am] * INV_LOG19;

    g_packed[i] = ((unsigned)am << 16)
                | (unsigned)__half_as_ushort(__float2half_rn(wpe));
}

// ============================================================================
// Fused passBC. Tile: 224 out-cols x 8 out-rows, grid (10,128).
// blockDim = 256 = W_IN (one vertical slider per thread).
// Phase 1.5 builds 8-column group sums so phase 2's 33-record prime
// collapses to 4 group-adds + 1 record-add. Interior tasks hoist the
// window-size math (fcount/invc/log2c) out of the 8-output loop.
// ============================================================================
#define W_OUT 224
#define W_IN  256                  // + 2*RAD halo columns == blockDim
#define HB    8                    // output rows per block
#define CHC_F 8                    // outputs per horizontal-slider task
#define NCHK  (W_OUT / CHC_F)      // 28 chunks per row
#define NGRP  (W_IN / CHC_F)       // 32 column-groups
#define STRIDE_A (W_IN * 4 + 4)    // 1028 words; %32==4 -> conflict-free
#define STRIDE_B (W_IN * 2 + 2)    // 514 words;  %32==2 -> conflict-free
#define GRP_WORDS 12               // 10 h-words + fs + pad (48B, 16B-aligned)
#define SMEM_WORDS (HB * (STRIDE_A + STRIDE_B) + NGRP * HB * GRP_WORDS)
#define SMEM_BYTES (SMEM_WORDS * 4)   // 61632 B -> 3 blocks/SM
#define SENT 0x00130000u           // class 19, wpe payload 0

__device__ __forceinline__ void pk_add(unsigned long long& w0,
                                       unsigned long long& w1,
                                       unsigned& w2, int cls) {
    if (cls < 8)       w0 += 1ull << (cls * 8);
    else if (cls < 16) w1 += 1ull << ((cls & 7) * 8);
    else               w2 += 1u << ((cls - 16) * 8);   // cls 19 -> spare byte 3
}
__device__ __forceinline__ void pk_sub(unsigned long long& w0,
                                       unsigned long long& w1,
                                       unsigned& w2, int cls) {
    if (cls < 8)       w0 -= 1ull << (cls * 8);
    else if (cls < 16) w1 -= 1ull << ((cls & 7) * 8);
    else               w2 -= 1u << ((cls - 16) * 8);
}

// unpack 4 bytes into two u32 halfword pairs
#define PLO(w) __byte_perm((w), 0, 0x4140)
#define PHI(w) __byte_perm((w), 0, 0x4342)

__device__ __forceinline__ float h2f_lo(unsigned u) {
    return __half2float(__ushort_as_half((unsigned short)u));
}

__device__ __forceinline__ void apply_add(uint4 a, uint2 b,
                                          unsigned* h, float& fs) {
    h[0] += PLO(a.x); h[1] += PHI(a.x);
    h[2] += PLO(a.y); h[3] += PHI(a.y);
    h[4] += PLO(a.z); h[5] += PHI(a.z);
    h[6] += PLO(a.w); h[7] += PHI(a.w);
    h[8] += PLO(b.x); h[9] += PHI(b.x);
    fs += __uint_as_float(b.y);
}
__device__ __forceinline__ void apply_sub(uint4 a, uint2 b,
                                          unsigned* h, float& fs) {
    h[0] -= PLO(a.x); h[1] -= PHI(a.x);
    h[2] -= PLO(a.y); h[3] -= PHI(a.y);
    h[4] -= PLO(a.z); h[5] -= PHI(a.z);
    h[6] -= PLO(a.w); h[7] -= PHI(a.w);
    h[8] -= PLO(b.x); h[9] -= PHI(b.x);
    fs -= __uint_as_float(b.y);
}

// add one h-format group record (12 words) to accumulators
__device__ __forceinline__ void grp_add(const unsigned* __restrict__ g,
                                        unsigned* h, float& fs) {
    uint4 a = *(const uint4*)g;
    uint4 b = *(const uint4*)(g + 4);
    uint4 c = *(const uint4*)(g + 8);
    h[0] += a.x; h[1] += a.y; h[2] += a.z; h[3] += a.w;
    h[4] += b.x; h[5] += b.y; h[6] += b.z; h[7] += b.w;
    h[8] += c.x; h[9] += c.y;
    fs += __uint_as_float(c.z);
}

__global__ __launch_bounds__(W_IN, 3) void fusedBC(float* __restrict__ out) {
    extern __shared__ unsigned sm[];
    unsigned* smA = sm;                          // HB * STRIDE_A words
    unsigned* smB = sm + HB * STRIDE_A;          // HB * STRIDE_B words
    unsigned* smG = smB + HB * STRIDE_B;         // NGRP*HB*GRP_WORDS words
    const int x0 = blockIdx.x * W_OUT;
    const int y0 = blockIdx.y * HB;
    const int tid = threadIdx.x;

    // ------------- Phase 1: vertical 33-tap sliders, branchless -------------
    {
        int xg = x0 - RAD + tid;
        bool xv = (xg >= 0) && (xg < WW);
        int xc = min(max(xg, 0), WW - 1);        // safe address, value gated

        unsigned long long w0 = 0, w1 = 0;
        unsigned w2 = 0;
        float fs = 0.f;
#pragma unroll
        for (int yi = 0; yi < 33; yi++) {
            int y = y0 - RAD + yi;
            bool inb = xv && (y >= 0) && (y < HH);
            unsigned u = inb ? g_packed[y * WW + xc] : SENT;
            fs += h2f_lo(u);
            pk_add(w0, w1, w2, (int)(u >> 16));
        }

        // batch all 16 slide words (MLP = 16)
        unsigned ua[HB], ud[HB];
#pragma unroll
        for (int r = 0; r < HB; r++) {
            int ya = y0 + r + RAD + 1;
            ua[r] = (xv && (ya < HH)) ? g_packed[ya * WW + xc] : SENT;
            int yr = y0 + r - RAD;
            ud[r] = (xv && (yr >= 0)) ? g_packed[yr * WW + xc] : SENT;
        }

#pragma unroll
        for (int r = 0; r < HB; r++) {
            *(uint4*)(smA + r * STRIDE_A + tid * 4) =
                make_uint4((unsigned)w0, (unsigned)(w0 >> 32),
                           (unsigned)w1, (unsigned)(w1 >> 32));
            *(uint2*)(smB + r * STRIDE_B + tid * 2) =
                make_uint2(w2, __float_as_uint(fs));
            fs += h2f_lo(ua[r]);
            pk_add(w0, w1, w2, (int)(ua[r] >> 16));
            fs -= h2f_lo(ud[r]);
            pk_sub(w0, w1, w2, (int)(ud[r] >> 16));
        }
    }
    __syncthreads();

    // ------------- Phase 1.5: 8-col group sums (256 tasks = 32g x 8r) -------
    {
        const int r = tid & 7;                   // low bits: conflict-free LDS
        const int g = tid >> 3;                  // 0..31
        const unsigned* rowA = smA + r * STRIDE_A;
        const unsigned* rowB = smB + r * STRIDE_B;

        unsigned h[10];
#pragma unroll
        for (int i = 0; i < 10; i++) h[i] = 0;
        float fs = 0.f;
#pragma unroll
        for (int k = 0; k < 8; k++) {
            int s = g * 8 + k;
            apply_add(*(const uint4*)(rowA + s * 4),
                      *(const uint2*)(rowB + s * 2), h, fs);
        }
        unsigned* dst = smG + (g * 8 + r) * GRP_WORDS;
        *(uint4*)dst       = make_uint4(h[0], h[1], h[2], h[3]);
        *(uint4*)(dst + 4) = make_uint4(h[4], h[5], h[6], h[7]);
        *(uint4*)(dst + 8) = make_uint4(h[8], h[9], __float_as_uint(fs), 0u);
    }
    __syncthreads();

    // ------------- Phase 2: horizontal sliders, software-pipelined ----------
    {
        const int r = tid & 7;      // low bits -> conflict-free LDS phases
        const int c = tid >> 3;     // 0..31; chunks >= NCHK idle
        const int xo = x0 + c * CHC_F;
        if (c < NCHK && xo < WW) {
            const unsigned* rowA = smA + r * STRIDE_A;
            const unsigned* rowB = smB + r * STRIDE_B;

            int yy = y0 + r;
            int wy = min(yy + RAD, HH - 1) - max(yy - RAD, 0) + 1;

            // interior tasks: wx == 33 for all 8 outputs -> hoist count math
            const bool interior = (xo >= RAD) && (xo + CHC_F - 1 + RAD < WW);
            float fcI  = (float)(33 * wy);
            float invcI = __frcp_rn(fcI);
            float l2cI  = __log2f(fcI);

            unsigned h[10];
#pragma unroll
            for (int i = 0; i < 10; i++) h[i] = 0;
            float fs = 0.f;

            // prime: groups c..c+3 cover records [8c, 8c+32), + record 8c+32
#pragma unroll
            for (int i = 0; i < 4; i++)
                grp_add(smG + ((c + i) * 8 + r) * GRP_WORDS, h, fs);
            {
                int s = c * CHC_F + 32;
                apply_add(*(const uint4*)(rowA + s * 4),
                          *(const uint2*)(rowB + s * 2), h, fs);
            }

            float s4[4], i4[4], u4[4];
#pragma unroll
            for (int k = 0; k < CHC_F; k++) {
                // ---- prefetch next slide's records BEFORE entropy ----
                uint4 aN, aO; uint2 bN, bO;
                if (k < CHC_F - 1) {
                    int sN = c * CHC_F + k + 33;
                    int sO = c * CHC_F + k;
                    aN = *(const uint4*)(rowA + sN * 4);
                    bN = *(const uint2*)(rowB + sN * 2);
                    aO = *(const uint4*)(rowA + sO * 4);
                    bO = *(const uint2*)(rowB + sO * 2);
                }

                // ---- entropy of current window (LDS latency hides here) ----
                float invc, l2c;
                if (interior) {
                    invc = invcI; l2c = l2cI;
                } else {
                    int x = xo + k;
                    int wx = min(x + RAD, WW - 1) - max(x - RAD, 0) + 1;
                    float fc = (float)(wx * wy);
                    invc = __frcp_rn(fc);
                    l2c  = __log2f(fc);
                }

                float acc0 = 0.f, acc1 = 0.f;      // two chains for ILP
#pragma unroll
                for (int p = 0; p < 10; p++) {
                    float slo = (float)(h[p] & 0xFFFFu);
                    float shi = (float)(h[p] >> 16);
                    acc0 += slo * __log2f(fmaxf(slo, 1.f));
                    if (p != 9)                    // lane 19 is pad/sentinel
                        acc1 += shi * __log2f(fmaxf(shi, 1.f));
                }
                float impurity = (l2c - (acc0 + acc1) * invc) * LOG2_TO_19;
                float unc = fs * invc;

                s4[k & 3] = impurity * unc;
                i4[k & 3] = impurity;
                u4[k & 3] = unc;

                if ((k & 3) == 3) {
                    int o = yy * WW + xo + (k & ~3);
                    *(float4*)(out + o)            = make_float4(s4[0], s4[1], s4[2], s4[3]);
                    *(float4*)(out + HWSZ + o)     = make_float4(i4[0], i4[1], i4[2], i4[3]);
                    *(float4*)(out + 2 * HWSZ + o) = make_float4(u4[0], u4[1], u4[2], u4[3]);
                }

                // ---- apply the prefetched slide ----
                if (k < CHC_F - 1) {
                    apply_add(aN, bN, h, fs);
                    apply_sub(aO, bO, h, fs);
                }
            }
        }
    }
}

// ============================================================================
extern "C" void kernel_launch(void* const* d_in, const int* in_sizes, int n_in,
                              void* d_out, int out_size) {
    const float* logit = (const float*)d_in[0];
    const float* cw    = (const float*)d_in[1];
    float* out = (float*)d_out;

    cudaFuncSetAttribute(fusedBC, cudaFuncAttributeMaxDynamicSharedMemorySize,
                         SMEM_BYTES);

    passA<<<HWSZ / 256, 256>>>(logit, cw);
    fusedBC<<<dim3((WW + W_OUT - 1) / W_OUT, HH / HB), W_IN, SMEM_BYTES>>>(out);
}

// round 14
// speedup vs baseline: 1.4952x; 1.0259x over previous
#include <cuda_runtime.h>
#include <cuda_bf16.h>
#include <cuda_fp16.h>

#define HH 1024
#define WW 2048
#define HWSZ (HH * WW)
#define NC 19
#define RAD 16
#define INV_LOG19 0.3396224f      // 1 / ln(19)
#define LOG2_TO_19 0.23541016f    // ln(2) / ln(19)

// -------- scratch (device globals: allocation-free per harness rules) -------
// packed per-pixel record: bits[16:21) = argmax class, bits[0:16) = fp16 wpe
__device__ unsigned g_packed[HWSZ];

// ============================================================================
// Pass A: 2 pixels/thread via float2 loads (MLP=2x19), packed 4B outputs
// ============================================================================
__global__ __launch_bounds__(256) void passA(const float2* __restrict__ logit2,
                                             const float* __restrict__ cw) {
    int i = blockIdx.x * blockDim.x + threadIdx.x;   // pair index
    if (i >= HWSZ / 2) return;

    float2 v[NC];
#pragma unroll
    for (int c = 0; c < NC; c++) v[c] = logit2[c * (HWSZ / 2) + i];

    unsigned outw[2];
#pragma unroll
    for (int l = 0; l < 2; l++) {
        float x[NC];
#pragma unroll
        for (int c = 0; c < NC; c++) x[c] = l ? v[c].y : v[c].x;

        float m = x[0];
        int am = 0;
#pragma unroll
        for (int c = 1; c < NC; c++) {
            if (x[c] > m) { m = x[c]; am = c; }
        }

        float S = 0.f, T = 0.f;
#pragma unroll
        for (int c = 0; c < NC; c++) {
            float d = x[c] - m;
            float e = __expf(d);
            S += e;
            T += e * d;
        }
        float ent = __logf(S) - T * __frcp_rn(S);
        float wpe = ent * cw[am] * INV_LOG19;

        outw[l] = ((unsigned)am << 16)
                | (unsigned)__half_as_ushort(__float2half_rn(wpe));
    }
    *(uint2*)(g_packed + 2 * i) = make_uint2(outw[0], outw[1]);
}

// ============================================================================
// Fused passBC. Tile: 192 out-cols x 8 out-rows, grid (11,128).
// blockDim = 224 = W_IN. smem 54KB + <=73 regs -> 4 blocks/SM (28 warps).
// Phase 1.5 group sums; phase 2 primes with 4 group-adds + 1 record-add.
// ============================================================================
#define W_OUT 192
#define W_IN  224                  // + 2*RAD halo columns == blockDim
#define HB    8                    // output rows per block
#define CHC_F 8                    // outputs per horizontal-slider task
#define NCHK  (W_OUT / CHC_F)      // 24 chunks per row
#define NGRP  (W_IN / CHC_F)       // 28 column-groups
#define STRIDE_A (W_IN * 4 + 4)    // 900 words; %32==4 -> conflict-free
#define STRIDE_B (W_IN * 2 + 2)    // 450 words; %32==2 -> conflict-free
#define GRP_WORDS 12               // 10 h-words + fs + pad (48B)
#define SMEM_WORDS (HB * (STRIDE_A + STRIDE_B) + NGRP * HB * GRP_WORDS)
#define SMEM_BYTES (SMEM_WORDS * 4)   // 53952 B -> 4 blocks/SM
#define SENT 0x00130000u           // class 19, wpe payload 0

__device__ __forceinline__ void pk_add(unsigned long long& w0,
                                       unsigned long long& w1,
                                       unsigned& w2, int cls) {
    if (cls < 8)       w0 += 1ull << (cls * 8);
    else if (cls < 16) w1 += 1ull << ((cls & 7) * 8);
    else               w2 += 1u << ((cls - 16) * 8);   // cls 19 -> spare byte 3
}
__device__ __forceinline__ void pk_sub(unsigned long long& w0,
                                       unsigned long long& w1,
                                       unsigned& w2, int cls) {
    if (cls < 8)       w0 -= 1ull << (cls * 8);
    else if (cls < 16) w1 -= 1ull << ((cls & 7) * 8);
    else               w2 -= 1u << ((cls - 16) * 8);
}

// unpack 4 bytes into two u32 halfword pairs
#define PLO(w) __byte_perm((w), 0, 0x4140)
#define PHI(w) __byte_perm((w), 0, 0x4342)

__device__ __forceinline__ float h2f_lo(unsigned u) {
    return __half2float(__ushort_as_half((unsigned short)u));
}

__device__ __forceinline__ void apply_add(uint4 a, uint2 b,
                                          unsigned* h, float& fs) {
    h[0] += PLO(a.x); h[1] += PHI(a.x);
    h[2] += PLO(a.y); h[3] += PHI(a.y);
    h[4] += PLO(a.z); h[5] += PHI(a.z);
    h[6] += PLO(a.w); h[7] += PHI(a.w);
    h[8] += PLO(b.x); h[9] += PHI(b.x);
    fs += __uint_as_float(b.y);
}
__device__ __forceinline__ void apply_sub(uint4 a, uint2 b,
                                          unsigned* h, float& fs) {
    h[0] -= PLO(a.x); h[1] -= PHI(a.x);
    h[2] -= PLO(a.y); h[3] -= PHI(a.y);
    h[4] -= PLO(a.z); h[5] -= PHI(a.z);
    h[6] -= PLO(a.w); h[7] -= PHI(a.w);
    h[8] -= PLO(b.x); h[9] -= PHI(b.x);
    fs -= __uint_as_float(b.y);
}

// add one h-format group record (12 words) to accumulators
__device__ __forceinline__ void grp_add(const unsigned* __restrict__ g,
                                        unsigned* h, float& fs) {
    uint4 a = *(const uint4*)g;
    uint4 b = *(const uint4*)(g + 4);
    uint4 c = *(const uint4*)(g + 8);
    h[0] += a.x; h[1] += a.y; h[2] += a.z; h[3] += a.w;
    h[4] += b.x; h[5] += b.y; h[6] += b.z; h[7] += b.w;
    h[8] += c.x; h[9] += c.y;
    fs += __uint_as_float(c.z);
}

__global__ __launch_bounds__(W_IN, 4) void fusedBC(float* __restrict__ out) {
    extern __shared__ unsigned sm[];
    unsigned* smA = sm;                          // HB * STRIDE_A words
    unsigned* smB = sm + HB * STRIDE_A;          // HB * STRIDE_B words
    unsigned* smG = smB + HB * STRIDE_B;         // NGRP*HB*GRP_WORDS words
    const int x0 = blockIdx.x * W_OUT;
    const int y0 = blockIdx.y * HB;
    const int tid = threadIdx.x;

    // ------------- Phase 1: vertical 33-tap sliders, branchless -------------
    {
        int xg = x0 - RAD + tid;
        bool xv = (xg >= 0) && (xg < WW);
        int xc = min(max(xg, 0), WW - 1);        // safe address, value gated

        unsigned long long w0 = 0, w1 = 0;
        unsigned w2 = 0;
        float fs = 0.f;
#pragma unroll
        for (int yi = 0; yi < 33; yi++) {
            int y = y0 - RAD + yi;
            bool inb = xv && (y >= 0) && (y < HH);
            unsigned u = inb ? g_packed[y * WW + xc] : SENT;
            fs += h2f_lo(u);
            pk_add(w0, w1, w2, (int)(u >> 16));
        }

        // batch all 16 slide words (MLP = 16)
        unsigned ua[HB], ud[HB];
#pragma unroll
        for (int r = 0; r < HB; r++) {
            int ya = y0 + r + RAD + 1;
            ua[r] = (xv && (ya < HH)) ? g_packed[ya * WW + xc] : SENT;
            int yr = y0 + r - RAD;
            ud[r] = (xv && (yr >= 0)) ? g_packed[yr * WW + xc] : SENT;
        }

#pragma unroll
        for (int r = 0; r < HB; r++) {
            *(uint4*)(smA + r * STRIDE_A + tid * 4) =
                make_uint4((unsigned)w0, (unsigned)(w0 >> 32),
                           (unsigned)w1, (unsigned)(w1 >> 32));
            *(uint2*)(smB + r * STRIDE_B + tid * 2) =
                make_uint2(w2, __float_as_uint(fs));
            fs += h2f_lo(ua[r]);
            pk_add(w0, w1, w2, (int)(ua[r] >> 16));
            fs -= h2f_lo(ud[r]);
            pk_sub(w0, w1, w2, (int)(ud[r] >> 16));
        }
    }
    __syncthreads();

    // ------------- Phase 1.5: 8-col group sums (224 tasks = 28g x 8r) -------
    {
        const int r = tid & 7;                   // low bits: conflict-free LDS
        const int g = tid >> 3;                  // 0..27
        const unsigned* rowA = smA + r * STRIDE_A;
        const unsigned* rowB = smB + r * STRIDE_B;

        unsigned h[10];
#pragma unroll
        for (int i = 0; i < 10; i++) h[i] = 0;
        float fs = 0.f;
#pragma unroll
        for (int k = 0; k < 8; k++) {
            int s = g * 8 + k;
            apply_add(*(const uint4*)(rowA + s * 4),
                      *(const uint2*)(rowB + s * 2), h, fs);
        }
        unsigned* dst = smG + (g * 8 + r) * GRP_WORDS;
        *(uint4*)dst       = make_uint4(h[0], h[1], h[2], h[3]);
        *(uint4*)(dst + 4) = make_uint4(h[4], h[5], h[6], h[7]);
        *(uint4*)(dst + 8) = make_uint4(h[8], h[9], __float_as_uint(fs), 0u);
    }
    __syncthreads();

    // ------------- Phase 2: horizontal sliders, software-pipelined ----------
    {
        const int r = tid & 7;      // low bits -> conflict-free LDS phases
        const int c = tid >> 3;     // 0..27; chunks >= NCHK idle
        const int xo = x0 + c * CHC_F;
        if (c < NCHK && xo < WW) {
            const unsigned* rowA = smA + r * STRIDE_A;
            const unsigned* rowB = smB + r * STRIDE_B;

            int yy = y0 + r;
            int wy = min(yy + RAD, HH - 1) - max(yy - RAD, 0) + 1;

            unsigned h[10];
#pragma unroll
            for (int i = 0; i < 10; i++) h[i] = 0;
            float fs = 0.f;

            // prime: groups c..c+3 cover records [8c, 8c+32), + record 8c+32
#pragma unroll
            for (int i = 0; i < 4; i++)
                grp_add(smG + ((c + i) * 8 + r) * GRP_WORDS, h, fs);
            {
                int s = c * CHC_F + 32;
                apply_add(*(const uint4*)(rowA + s * 4),
                          *(const uint2*)(rowB + s * 2), h, fs);
            }

            float s4[4], i4[4], u4[4];
#pragma unroll
            for (int k = 0; k < CHC_F; k++) {
                // ---- prefetch the incoming record BEFORE entropy ----
                uint4 aN; uint2 bN;
                if (k < CHC_F - 1) {
                    int sN = c * CHC_F + k + 33;
                    aN = *(const uint4*)(rowA + sN * 4);
                    bN = *(const uint2*)(rowB + sN * 2);
                }

                // ---- entropy of current window (LDS latency hides here) ----
                int x = xo + k;
                int wx = min(x + RAD, WW - 1) - max(x - RAD, 0) + 1;
                float fc = (float)(wx * wy);       // exact window size
                float invc = __frcp_rn(fc);
                float l2c  = __log2f(fc);

                float acc0 = 0.f, acc1 = 0.f;      // two chains for ILP
#pragma unroll
                for (int p = 0; p < 10; p++) {
                    float slo = (float)(h[p] & 0xFFFFu);
                    float shi = (float)(h[p] >> 16);
                    acc0 += slo * __log2f(fmaxf(slo, 1.f));
                    if (p != 9)                    // lane 19 is pad/sentinel
                        acc1 += shi * __log2f(fmaxf(shi, 1.f));
                }
                float impurity = (l2c - (acc0 + acc1) * invc) * LOG2_TO_19;
                float unc = fs * invc;

                s4[k & 3] = impurity * unc;
                i4[k & 3] = impurity;
                u4[k & 3] = unc;

                if ((k & 3) == 3) {
                    int o = yy * WW + xo + (k & ~3);
                    *(float4*)(out + o)            = make_float4(s4[0], s4[1], s4[2], s4[3]);
                    *(float4*)(out + HWSZ + o)     = make_float4(i4[0], i4[1], i4[2], i4[3]);
                    *(float4*)(out + 2 * HWSZ + o) = make_float4(u4[0], u4[1], u4[2], u4[3]);
                }

                // ---- slide: prefetched add, direct-smem sub ----
                if (k < CHC_F - 1) {
                    apply_add(aN, bN, h, fs);
                    int sO = c * CHC_F + k;
                    apply_sub(*(const uint4*)(rowA + sO * 4),
                              *(const uint2*)(rowB + sO * 2), h, fs);
                }
            }
        }
    }
}

// ============================================================================
extern "C" void kernel_launch(void* const* d_in, const int* in_sizes, int n_in,
                              void* d_out, int out_size) {
    const float* logit = (const float*)d_in[0];
    const float* cw    = (const float*)d_in[1];
    float* out = (float*)d_out;

    cudaFuncSetAttribute(fusedBC, cudaFuncAttributeMaxDynamicSharedMemorySize,
                         SMEM_BYTES);

    passA<<<(HWSZ / 2 + 255) / 256, 256>>>((const float2*)logit, cw);
    fusedBC<<<dim3((WW + W_OUT - 1) / W_OUT, HH / HB), W_IN, SMEM_BYTES>>>(out);
}